// round 1
// baseline (speedup 1.0000x reference)
#include <cuda_runtime.h>

#define B_   4
#define S_   2048
#define D_   512
#define H_   8
#define DK_  64

// Scratch (allocation-free: __device__ globals)
__device__ float g_Qh[B_*H_*S_*DK_];
__device__ float g_Kh[B_*H_*S_*DK_];
__device__ float g_Vh[B_*H_*S_*DK_];
__device__ float g_Oc[B_*S_*D_];     // attention output, head-concat layout [B*S, 512]

// ---------------------------------------------------------------------------
// Projection: Y[b,h,s,k] = sum_d X[b,s,d] * W[h,d,k]
// grid = (H, (B*S)/64), block = 256. Each block: 64 rows x one head (64 cols).
// ---------------------------------------------------------------------------
__global__ __launch_bounds__(256) void proj_kernel(const float* __restrict__ X,
                                                   const float* __restrict__ W,
                                                   int which)
{
    float* __restrict__ Y = (which == 0) ? g_Qh : (which == 1) ? g_Kh : g_Vh;

    __shared__ float As[64][33];   // A tile [m][k], padded
    __shared__ float Bs[32][68];   // B tile [k][n], padded, float4-aligned cols

    const int h  = blockIdx.x;
    const int m0 = blockIdx.y * 64;
    const int tid = threadIdx.x;
    const int tx = tid & 15, ty = tid >> 4;

    const float* __restrict__ Wh = W + (size_t)h * (D_ * DK_);

    float acc[4][4] = {};

    for (int k0 = 0; k0 < D_; k0 += 32) {
        // load A 64x32 (float4 global, scalar smem stores)
        {
            int f = tid;
            #pragma unroll
            for (int it = 0; it < 2; it++, f += 256) {
                int r = f >> 3, c4 = (f & 7) << 2;
                float4 v = *(const float4*)(X + (size_t)(m0 + r) * D_ + k0 + c4);
                As[r][c4+0] = v.x; As[r][c4+1] = v.y;
                As[r][c4+2] = v.z; As[r][c4+3] = v.w;
            }
        }
        // load B 32x64 from W[h][d][k] (float4 both sides)
        {
            int f = tid;
            #pragma unroll
            for (int it = 0; it < 2; it++, f += 256) {
                int c = f >> 4, k4 = (f & 15) << 2;
                *(float4*)&Bs[c][k4] = *(const float4*)(Wh + (size_t)(k0 + c) * DK_ + k4);
            }
        }
        __syncthreads();

        #pragma unroll
        for (int kk = 0; kk < 32; kk++) {
            float4 b4 = *(const float4*)&Bs[kk][tx * 4];
            #pragma unroll
            for (int i = 0; i < 4; i++) {
                float a = As[ty * 4 + i][kk];
                acc[i][0] += a * b4.x;
                acc[i][1] += a * b4.y;
                acc[i][2] += a * b4.z;
                acc[i][3] += a * b4.w;
            }
        }
        __syncthreads();
    }

    #pragma unroll
    for (int i = 0; i < 4; i++) {
        int m = m0 + ty * 4 + i;
        int b = m / S_, s = m % S_;
        float4 v = make_float4(acc[i][0], acc[i][1], acc[i][2], acc[i][3]);
        *(float4*)(Y + ((size_t)((b * H_ + h) * S_ + s)) * DK_ + tx * 4) = v;
    }
}

// ---------------------------------------------------------------------------
// Flash attention per (b, h, q-block of 64). Online softmax, dk = 64.
// Dynamic smem: Qs | Kt (transposed) | Vs | Ps, each 64x68 floats.
// ---------------------------------------------------------------------------
__global__ __launch_bounds__(256) void attn_kernel()
{
    extern __shared__ float sm[];
    float (*Qs)[68] = (float(*)[68])(sm);
    float (*Kt)[68] = (float(*)[68])(sm + 1 * 64 * 68);  // Kt[k][s]
    float (*Vs)[68] = (float(*)[68])(sm + 2 * 64 * 68);  // Vs[s][k]
    float (*Ps)[68] = (float(*)[68])(sm + 3 * 64 * 68);  // Ps[q][s]

    const int q0 = blockIdx.x * 64;
    const int h  = blockIdx.y;
    const int b  = blockIdx.z;

    const float* __restrict__ Qb = g_Qh + ((size_t)(b * H_ + h) * S_) * DK_;
    const float* __restrict__ Kb = g_Kh + ((size_t)(b * H_ + h) * S_) * DK_;
    const float* __restrict__ Vb = g_Vh + ((size_t)(b * H_ + h) * S_) * DK_;

    const int tid = threadIdx.x;
    const int tx = tid & 15, ty = tid >> 4;

    // Load Q tile (64x64)
    {
        int f = tid;
        #pragma unroll
        for (int it = 0; it < 4; it++, f += 256) {
            int r = f >> 4, k4 = (f & 15) << 2;
            *(float4*)&Qs[r][k4] = *(const float4*)(Qb + (size_t)(q0 + r) * DK_ + k4);
        }
    }

    float accO[4][4] = {};
    float mrun[4], lrun[4];
    #pragma unroll
    for (int i = 0; i < 4; i++) { mrun[i] = -1e30f; lrun[i] = 0.f; }

    const float Cc = 0.125f * 1.4426950408889634f;   // (1/sqrt(64)) * log2(e)

    for (int s0 = 0; s0 < S_; s0 += 64) {
        // Load K (transposed into Kt[k][s]) and V (natural)
        {
            int f = tid;
            #pragma unroll
            for (int it = 0; it < 4; it++, f += 256) {
                int r = f >> 4, k4 = (f & 15) << 2;
                float4 kv = *(const float4*)(Kb + (size_t)(s0 + r) * DK_ + k4);
                Kt[k4+0][r] = kv.x; Kt[k4+1][r] = kv.y;
                Kt[k4+2][r] = kv.z; Kt[k4+3][r] = kv.w;
                *(float4*)&Vs[r][k4] = *(const float4*)(Vb + (size_t)(s0 + r) * DK_ + k4);
            }
        }
        __syncthreads();

        // Scores: S[i][j] = sum_k Q[i][k] * K[j][k]
        float sacc[4][4] = {};
        #pragma unroll
        for (int k = 0; k < 64; k++) {
            float4 k4v = *(const float4*)&Kt[k][tx * 4];
            #pragma unroll
            for (int i = 0; i < 4; i++) {
                float q = Qs[ty * 4 + i][k];
                sacc[i][0] += q * k4v.x;
                sacc[i][1] += q * k4v.y;
                sacc[i][2] += q * k4v.z;
                sacc[i][3] += q * k4v.w;
            }
        }

        // Online softmax (row groups of 16 lanes: tx = lane bits 0..3)
        #pragma unroll
        for (int i = 0; i < 4; i++) {
            float mloc = fmaxf(fmaxf(sacc[i][0], sacc[i][1]),
                               fmaxf(sacc[i][2], sacc[i][3]));
            #pragma unroll
            for (int off = 8; off >= 1; off >>= 1)
                mloc = fmaxf(mloc, __shfl_xor_sync(0xffffffffu, mloc, off));

            float mnew  = fmaxf(mrun[i], mloc);
            float scale = exp2f((mrun[i] - mnew) * Cc);
            float p0 = exp2f((sacc[i][0] - mnew) * Cc);
            float p1 = exp2f((sacc[i][1] - mnew) * Cc);
            float p2 = exp2f((sacc[i][2] - mnew) * Cc);
            float p3 = exp2f((sacc[i][3] - mnew) * Cc);

            float rs = (p0 + p1) + (p2 + p3);
            #pragma unroll
            for (int off = 8; off >= 1; off >>= 1)
                rs += __shfl_xor_sync(0xffffffffu, rs, off);

            lrun[i] = lrun[i] * scale + rs;
            mrun[i] = mnew;
            accO[i][0] *= scale; accO[i][1] *= scale;
            accO[i][2] *= scale; accO[i][3] *= scale;

            *(float4*)&Ps[ty * 4 + i][tx * 4] = make_float4(p0, p1, p2, p3);
        }
        __syncthreads();

        // O += P @ V
        #pragma unroll
        for (int s = 0; s < 64; s++) {
            float4 v4 = *(const float4*)&Vs[s][tx * 4];
            #pragma unroll
            for (int i = 0; i < 4; i++) {
                float p = Ps[ty * 4 + i][s];
                accO[i][0] += p * v4.x;
                accO[i][1] += p * v4.y;
                accO[i][2] += p * v4.z;
                accO[i][3] += p * v4.w;
            }
        }
        __syncthreads();
    }

    // Epilogue: normalize and write head-concat layout [b*S + q, h*64 + k]
    #pragma unroll
    for (int i = 0; i < 4; i++) {
        float inv = 1.f / lrun[i];
        float4 v = make_float4(accO[i][0] * inv, accO[i][1] * inv,
                               accO[i][2] * inv, accO[i][3] * inv);
        *(float4*)(g_Oc + (size_t)(b * S_ + q0 + ty * 4 + i) * D_ + h * DK_ + tx * 4) = v;
    }
}

// ---------------------------------------------------------------------------
// Output projection: out[m, n] = sum_d Oc[m, d] * WO[d, n]  (8192x512x512)
// grid = (512/64, 8192/64), block = 256.
// ---------------------------------------------------------------------------
__global__ __launch_bounds__(256) void gemm_out_kernel(const float* __restrict__ WO,
                                                       float* __restrict__ out)
{
    __shared__ float As[64][33];
    __shared__ float Bs[32][68];

    const int n0 = blockIdx.x * 64;
    const int m0 = blockIdx.y * 64;
    const int tid = threadIdx.x;
    const int tx = tid & 15, ty = tid >> 4;

    float acc[4][4] = {};

    for (int k0 = 0; k0 < D_; k0 += 32) {
        {
            int f = tid;
            #pragma unroll
            for (int it = 0; it < 2; it++, f += 256) {
                int r = f >> 3, c4 = (f & 7) << 2;
                float4 v = *(const float4*)(g_Oc + (size_t)(m0 + r) * D_ + k0 + c4);
                As[r][c4+0] = v.x; As[r][c4+1] = v.y;
                As[r][c4+2] = v.z; As[r][c4+3] = v.w;
            }
        }
        {
            int f = tid;
            #pragma unroll
            for (int it = 0; it < 2; it++, f += 256) {
                int c = f >> 4, k4 = (f & 15) << 2;
                *(float4*)&Bs[c][k4] = *(const float4*)(WO + (size_t)(k0 + c) * D_ + n0 + k4);
            }
        }
        __syncthreads();

        #pragma unroll
        for (int kk = 0; kk < 32; kk++) {
            float4 b4 = *(const float4*)&Bs[kk][tx * 4];
            #pragma unroll
            for (int i = 0; i < 4; i++) {
                float a = As[ty * 4 + i][kk];
                acc[i][0] += a * b4.x;
                acc[i][1] += a * b4.y;
                acc[i][2] += a * b4.z;
                acc[i][3] += a * b4.w;
            }
        }
        __syncthreads();
    }

    #pragma unroll
    for (int i = 0; i < 4; i++) {
        int m = m0 + ty * 4 + i;
        float4 v = make_float4(acc[i][0], acc[i][1], acc[i][2], acc[i][3]);
        *(float4*)(out + (size_t)m * D_ + n0 + tx * 4) = v;
    }
}

// ---------------------------------------------------------------------------
extern "C" void kernel_launch(void* const* d_in, const int* in_sizes, int n_in,
                              void* d_out, int out_size)
{
    const float* Q  = (const float*)d_in[0];
    const float* K  = (const float*)d_in[1];
    const float* V  = (const float*)d_in[2];
    const float* WQ = (const float*)d_in[3];
    const float* WK = (const float*)d_in[4];
    const float* WV = (const float*)d_in[5];
    const float* WO = (const float*)d_in[6];
    float* out = (float*)d_out;

    dim3 pgrid(H_, (B_ * S_) / 64);
    proj_kernel<<<pgrid, 256>>>(Q, WQ, 0);
    proj_kernel<<<pgrid, 256>>>(K, WK, 1);
    proj_kernel<<<pgrid, 256>>>(V, WV, 2);

    size_t smem = (size_t)4 * 64 * 68 * sizeof(float);   // 69632 B
    cudaFuncSetAttribute(attn_kernel,
                         cudaFuncAttributeMaxDynamicSharedMemorySize, (int)smem);
    attn_kernel<<<dim3(S_ / 64, H_, B_), 256, smem>>>();

    gemm_out_kernel<<<dim3(D_ / 64, (B_ * S_) / 64), 256>>>(WO, out);
}